// round 12
// baseline (speedup 1.0000x reference)
#include <cuda_runtime.h>
#include <math.h>
#include <stdint.h>

#ifndef M_PI
#define M_PI 3.14159265358979323846
#endif

#define S_LEN 128
#define B_SZ  128
#define T_OUT 12
#define NSAMP (S_LEN * B_SZ)   // 16384
#define N_OPS 30

#define NBLK       148
#define NLSTM      128          // blocks 0..127 carry one LSTM warp each (wid 15)
#define NWARP_WORK 2240         // 128*15 + 20*16
#define THREADS    512
#define N_ITEMS    4096         // embed items (4 samples each), s-major

// ---------------------------------------------------------------------------
// Scratch + progress counters (device globals; no allocation allowed)
// ---------------------------------------------------------------------------
__device__ float g_zx[NSAMP * 32];      // [s*B+b][g*8+q]
__device__ float g_h [NSAMP * 8];       // [s*B+b][h]
__device__ unsigned g_emb_chunk[8];     // 512 items per 16-s chunk
__device__ unsigned g_lstm_s[S_LEN];    // 128 warp-arrivals per s

struct QOps {
    int   kind[N_OPS];   // 0=rx, 1=ry, 2=rz, 3=cnot
    int   pa[N_OPS];     // bit position of wire (rot) / control (cnot); <5 lane, >=5 k
    int   pb[N_OPS];     // bit position of target (cnot)
    float c[N_OPS];      // cos(theta/2)
    float s[N_OPS];      // sin(theta/2)
    int   ord[8];        // ord[j] = wire living at bit position j
};

// ---------------------------------------------------------------------------
// Sync + math helpers
// ---------------------------------------------------------------------------
__device__ __forceinline__ unsigned ld_acq(const unsigned* p) {
    unsigned v;
    asm volatile("ld.acquire.gpu.global.u32 %0, [%1];" : "=r"(v) : "l"(p));
    return v;
}
__device__ __forceinline__ void red_rel(unsigned* p) {
    asm volatile("red.release.gpu.global.add.u32 [%0], 1;" :: "l"(p) : "memory");
}
__device__ __forceinline__ float fast_sigmoid(float x) {
    return __fdividef(1.f, 1.f + __expf(-x));
}
__device__ __forceinline__ float fast_tanh(float x) {
    x = fminf(fmaxf(x, -15.f), 15.f);
    float t = __expf(2.f * x);
    return __fdividef(t - 1.f, t + 1.f);
}

// ---------------------------------------------------------------------------
// Init kernel: zero progress counters (every call / graph replay)
// ---------------------------------------------------------------------------
__global__ void k_init() {
    int t = threadIdx.x;
    if (t < 8)      g_emb_chunk[t] = 0;
    if (t < S_LEN)  g_lstm_s[t]    = 0;
}

// ---------------------------------------------------------------------------
// LSTM warp: one warp per batch element b (wid 15 of block b -> top arbiter
// priority on its SM). Horner form for the gate projection.
// ---------------------------------------------------------------------------
__device__ void lstm_warp(int b, int l,
                          const float* __restrict__ Win,
                          const float* __restrict__ Wout,
                          const float* __restrict__ b_out)
{
    const unsigned FULL = 0xffffffffu;
    int g = l >> 3, h = l & 7;

    float winh[8], wo[8];
    #pragma unroll
    for (int j = 0; j < 8; j++) {
        winh[j] = Win[l * 72 + 64 + j];
        wo[j]   = Wout[(g * 8 + h) * 8 + j];
    }
    float bo = b_out[g * 8 + h];

    float cst = 0.f, hh = 0.f, zbuf = 0.f;
    for (int s = 0; s < S_LEN; s++) {
        float z;
        if ((s & 15) == 0) {
            unsigned* ch = &g_emb_chunk[s >> 4];
            while (ld_acq(ch) < 512u) __nanosleep(32);
            z = __ldcg(&g_zx[(s * B_SZ + b) * 32 + l]);
        } else {
            z = zbuf;
        }
        if ((s & 15) != 15)    // s+1 is inside the already-confirmed chunk
            zbuf = __ldcg(&g_zx[((s + 1) * B_SZ + b) * 32 + l]);

        #pragma unroll
        for (int j = 0; j < 8; j++)
            z = fmaf(__shfl_sync(FULL, hh, j), winh[j], z);

        float cz = __cosf(z);
        float cj[8];
        #pragma unroll
        for (int j = 0; j < 8; j++)
            cj[j] = __shfl_sync(FULL, cz, (g << 3) | j);

        // pre = bo + c0*(W0 + c1*(W1 + ... + c7*W7)) == sum_q W_q * cumprod_q
        float t = wo[7];
        #pragma unroll
        for (int j = 6; j >= 0; j--)
            t = fmaf(cj[j + 1], t, wo[j]);
        float pre = fmaf(cj[0], t, bo);

        float pf = __shfl_sync(FULL, pre, h);
        float pi = __shfl_sync(FULL, pre, 8  | h);
        float pg = __shfl_sync(FULL, pre, 16 | h);
        float po = __shfl_sync(FULL, pre, 24 | h);

        float fg = fast_sigmoid(pf);
        float ig = fast_sigmoid(pi);
        float gg = fast_tanh(pg);
        float og = fast_sigmoid(po);

        cst = fmaf(fg, cst, ig * gg);
        hh  = og * fast_tanh(cst);

        if (l < 8) g_h[(s * B_SZ + b) * 8 + l] = hh;
        __syncwarp();
        if (l == 0) red_rel(&g_lstm_s[s]);   // release: h(s, b) published
    }
}

// ---------------------------------------------------------------------------
// QFC per sample r (s-major: s = r>>7, b = r&127). Register statevector.
// ---------------------------------------------------------------------------
#define RXP(i,j) do { float nx0=c*ax[i]+sn*ay[j], ny0=c*ay[i]-sn*ax[j]; \
                      float nx1=c*ax[j]+sn*ay[i], ny1=c*ay[j]-sn*ax[i]; \
                      ax[i]=nx0; ay[i]=ny0; ax[j]=nx1; ay[j]=ny1; } while(0)
#define RYP(i,j) do { float nx0=c*ax[i]-sn*ax[j], ny0=c*ay[i]-sn*ay[j]; \
                      float nx1=sn*ax[i]+c*ax[j], ny1=sn*ay[i]+c*ay[j]; \
                      ax[i]=nx0; ay[i]=ny0; ax[j]=nx1; ay[j]=ny1; } while(0)
#define SWP(i,j) do { float tx=ax[i]; ax[i]=ax[j]; ax[j]=tx; \
                      float ty=ay[i]; ay[i]=ay[j]; ay[j]=ty; } while(0)
#define PAIRS_SWITCH(kb, APPLY) \
    switch (kb) { \
      case 0:  APPLY(0,1); APPLY(2,3); APPLY(4,5); APPLY(6,7); break; \
      case 1:  APPLY(0,2); APPLY(1,3); APPLY(4,6); APPLY(5,7); break; \
      default: APPLY(0,4); APPLY(1,5); APPLY(2,6); APPLY(3,7); break; \
    }

__device__ void qfc_sample(int r, int l, const QOps& ops,
                           const float* __restrict__ phiq,
                           const float* __restrict__ Whead,
                           const float* __restrict__ b_head,
                           float* __restrict__ out)
{
    const unsigned FULL = 0xffffffffu;
    int s = r >> 7, b = r & 127;

    const float* th = &g_h[(s * B_SZ + b) * 8];
    float cw[8], sw[8];
    #pragma unroll
    for (int j = 0; j < 8; j++) {
        float v = __ldcg(&th[ops.ord[j]]);       // wire at bit position j
        __sincosf(0.5f * v, &sw[j], &cw[j]);
    }

    // Product-state init (bit position j<5 -> lane bit j, j>=5 -> k bit j-5)
    float base = 1.f;
    #pragma unroll
    for (int j = 0; j < 5; j++)
        base *= ((l >> j) & 1) ? sw[j] : cw[j];

    float ax[8], ay[8];
    #pragma unroll
    for (int k = 0; k < 8; k++) {
        float t = ((k      & 1) ? sw[5] : cw[5]) *
                  (((k >> 1) & 1) ? sw[6] : cw[6]) *
                  (((k >> 2) & 1) ? sw[7] : cw[7]);
        ax[k] = base * t;
        ay[k] = 0.f;
    }

    // 30 random ops + 8 trainable RX(phiq) — uniform control flow
    for (int op = 0; op < N_OPS + 8; op++) {
        int kind, pa, pb_;
        float c, sn;
        if (op < N_OPS) {
            kind = ops.kind[op];
            pa   = ops.pa[op];
            pb_  = ops.pb[op];
            c    = ops.c[op];
            sn   = ops.s[op];
        } else {
            int e = op - N_OPS;
            kind = 0; pa = e; pb_ = 0;
            __sincosf(0.5f * phiq[ops.ord[e]], &sn, &c);
        }

        if (kind == 3) {                              // ---- CNOT ----
            int pc = pa, pt = pb_;
            if (pc < 5 && pt < 5) {
                unsigned m = 1u << pt;
                bool ctl = (l >> pc) & 1;
                #pragma unroll
                for (int k = 0; k < 8; k++) {
                    float qx = __shfl_xor_sync(FULL, ax[k], m);
                    float qy = __shfl_xor_sync(FULL, ay[k], m);
                    if (ctl) { ax[k] = qx; ay[k] = qy; }
                }
            } else if (pc < 5) {
                bool ctl = (l >> pc) & 1;
                if (ctl) { PAIRS_SWITCH(pt - 5, SWP); }
            } else if (pt < 5) {
                unsigned m = 1u << pt;
                int ckb = pc - 5;
                #pragma unroll
                for (int k = 0; k < 8; k++) {
                    float qx = __shfl_xor_sync(FULL, ax[k], m);
                    float qy = __shfl_xor_sync(FULL, ay[k], m);
                    if ((k >> ckb) & 1) { ax[k] = qx; ay[k] = qy; }
                }
            } else {
                int ckb = pc - 5, tkb = pt - 5;
                switch (ckb * 4 + tkb) {
                  case 1:  SWP(1,3); SWP(5,7); break;
                  case 2:  SWP(1,5); SWP(3,7); break;
                  case 4:  SWP(2,3); SWP(6,7); break;
                  case 6:  SWP(2,6); SWP(3,7); break;
                  case 8:  SWP(4,5); SWP(6,7); break;
                  default: SWP(4,6); SWP(5,7); break;
                }
            }
        } else if (kind == 2) {                       // ---- RZ ----
            if (pa < 5) {
                float sg = ((l >> pa) & 1) ? -sn : sn;
                #pragma unroll
                for (int k = 0; k < 8; k++) {
                    float x = ax[k], y = ay[k];
                    ax[k] = c * x + sg * y;
                    ay[k] = c * y - sg * x;
                }
            } else {
                int kb = pa - 5;
                #pragma unroll
                for (int k = 0; k < 8; k++) {
                    float sg = ((k >> kb) & 1) ? -sn : sn;
                    float x = ax[k], y = ay[k];
                    ax[k] = c * x + sg * y;
                    ay[k] = c * y - sg * x;
                }
            }
        } else if (kind == 1) {                       // ---- RY ----
            if (pa < 5) {
                unsigned m = 1u << pa;
                float sg = ((l >> pa) & 1) ? sn : -sn;
                #pragma unroll
                for (int k = 0; k < 8; k++) {
                    float px = __shfl_xor_sync(FULL, ax[k], m);
                    float py = __shfl_xor_sync(FULL, ay[k], m);
                    ax[k] = c * ax[k] + sg * px;
                    ay[k] = c * ay[k] + sg * py;
                }
            } else {
                PAIRS_SWITCH(pa - 5, RYP);
            }
        } else {                                      // ---- RX ----
            if (pa < 5) {
                unsigned m = 1u << pa;
                #pragma unroll
                for (int k = 0; k < 8; k++) {
                    float px = __shfl_xor_sync(FULL, ax[k], m);
                    float py = __shfl_xor_sync(FULL, ay[k], m);
                    ax[k] = c * ax[k] + sn * py;
                    ay[k] = c * ay[k] - sn * px;
                }
            } else {
                PAIRS_SWITCH(pa - 5, RXP);
            }
        }
    }

    // Measure <Z> per bit position
    float pb4[8];
    #pragma unroll
    for (int k = 0; k < 8; k++) pb4[k] = ax[k] * ax[k] + ay[k] * ay[k];

    float P = ((pb4[0] + pb4[1]) + (pb4[2] + pb4[3])) +
              ((pb4[4] + pb4[5]) + (pb4[6] + pb4[7]));
    float mb0 = (pb4[0] + pb4[2] + pb4[4] + pb4[6]) - (pb4[1] + pb4[3] + pb4[5] + pb4[7]);
    float mb1 = (pb4[0] + pb4[1] + pb4[4] + pb4[5]) - (pb4[2] + pb4[3] + pb4[6] + pb4[7]);
    float mb2 = (pb4[0] + pb4[1] + pb4[2] + pb4[3]) - (pb4[4] + pb4[5] + pb4[6] + pb4[7]);

    float z[8];
    #pragma unroll
    for (int j = 0; j < 5; j++)
        z[j] = ((l >> j) & 1) ? -P : P;
    z[5] = mb0; z[6] = mb1; z[7] = mb2;

    #pragma unroll
    for (int off = 16; off >= 1; off >>= 1) {
        #pragma unroll
        for (int j = 0; j < 8; j++)
            z[j] += __shfl_xor_sync(FULL, z[j], off);
    }

    // Head + log_softmax (lanes 0..11); permutation folded into Whead index
    float lg = -INFINITY;
    if (l < T_OUT) {
        lg = b_head[l];
        #pragma unroll
        for (int j = 0; j < 8; j++)
            lg = fmaf(Whead[l * 8 + ops.ord[j]], z[j], lg);
    }
    float m = lg;
    #pragma unroll
    for (int off = 16; off >= 1; off >>= 1)
        m = fmaxf(m, __shfl_xor_sync(FULL, m, off));
    float e = (l < T_OUT) ? expf(lg - m) : 0.f;
    float se = e;
    #pragma unroll
    for (int off = 16; off >= 1; off >>= 1)
        se += __shfl_xor_sync(FULL, se, off);

    if (l < T_OUT)
        out[(b * S_LEN + s) * T_OUT + l] = lg - m - logf(se);
}

// ---------------------------------------------------------------------------
// Fused kernel: 148 blocks x 512 threads, 1 CTA/SM (wave-1 resident).
// Blocks 0..127: wid 15 = LSTM warp for batch b = blockIdx.x (top arbiter
// priority), wid 0..14 = workers. Blocks 128..147: 16 worker warps.
// Workers: embed phase (items s-major) then qfc phase (samples s-major).
// ---------------------------------------------------------------------------
__global__ void __launch_bounds__(THREADS, 1) k_fused(
        const float* __restrict__ emb,
        const float* __restrict__ Win,
        const float* __restrict__ b_in,
        const float* __restrict__ phi,
        const float* __restrict__ Wout,
        const float* __restrict__ b_out,
        const float* __restrict__ phiq,
        const float* __restrict__ Whead,
        const float* __restrict__ b_head,
        const void*  __restrict__ sent_raw,
        float* __restrict__ out,
        QOps ops)
{
    int tid = threadIdx.x, wid = tid >> 5, l = tid & 31;

    __shared__ float winT[64 * 32];         // [e][l]
    __shared__ float bp[32];
    for (int k = tid; k < 64 * 32; k += THREADS) {
        int e = k >> 5, ll = k & 31;
        winT[k] = Win[ll * 72 + e];
    }
    if (tid < 32) bp[tid] = b_in[tid] + phi[tid];
    __syncthreads();                        // all 16 warps participate (once)

    if (blockIdx.x < NLSTM && wid == 15) {
        lstm_warp(blockIdx.x, l, Win, Wout, b_out);
        return;
    }

    // worker warp global index (0..2239)
    int wq = (blockIdx.x < NLSTM)
           ? blockIdx.x * 15 + wid
           : NLSTM * 15 + (blockIdx.x - NLSTM) * 16 + wid;

    // dtype sniff: int64 sentence has all-zero high words (tokens < 30000)
    const int* si = (const int*)sent_raw;
    bool is64 = true;
    #pragma unroll
    for (int k = 0; k < 16; k++)
        if (si[2 * k + 1] != 0) is64 = false;

    // ---- embed: items of 4 s-major samples ----
    for (int item = wq; item < N_ITEMS; item += NWARP_WORK) {
        int sm0 = item * 4;
        long long t0 = is64 ? ((const long long*)sent_raw)[sm0 + 0] : (long long)si[sm0 + 0];
        long long t1 = is64 ? ((const long long*)sent_raw)[sm0 + 1] : (long long)si[sm0 + 1];
        long long t2 = is64 ? ((const long long*)sent_raw)[sm0 + 2] : (long long)si[sm0 + 2];
        long long t3 = is64 ? ((const long long*)sent_raw)[sm0 + 3] : (long long)si[sm0 + 3];
        const float4* e0 = (const float4*)(emb + t0 * 64);
        const float4* e1 = (const float4*)(emb + t1 * 64);
        const float4* e2 = (const float4*)(emb + t2 * 64);
        const float4* e3 = (const float4*)(emb + t3 * 64);

        float a0 = bp[l], a1 = a0, a2 = a0, a3 = a0;
        #pragma unroll
        for (int e4 = 0; e4 < 16; e4++) {
            float4 v0 = e0[e4], v1 = e1[e4], v2 = e2[e4], v3 = e3[e4];
            float w0 = winT[(e4 * 4 + 0) * 32 + l];
            float w1 = winT[(e4 * 4 + 1) * 32 + l];
            float w2 = winT[(e4 * 4 + 2) * 32 + l];
            float w3 = winT[(e4 * 4 + 3) * 32 + l];
            a0 = fmaf(v0.x, w0, fmaf(v0.y, w1, fmaf(v0.z, w2, fmaf(v0.w, w3, a0))));
            a1 = fmaf(v1.x, w0, fmaf(v1.y, w1, fmaf(v1.z, w2, fmaf(v1.w, w3, a1))));
            a2 = fmaf(v2.x, w0, fmaf(v2.y, w1, fmaf(v2.z, w2, fmaf(v2.w, w3, a2))));
            a3 = fmaf(v3.x, w0, fmaf(v3.y, w1, fmaf(v3.z, w2, fmaf(v3.w, w3, a3))));
        }
        g_zx[(sm0 + 0) * 32 + l] = a0;
        g_zx[(sm0 + 1) * 32 + l] = a1;
        g_zx[(sm0 + 2) * 32 + l] = a2;
        g_zx[(sm0 + 3) * 32 + l] = a3;
        __syncwarp();
        if (l == 0) red_rel(&g_emb_chunk[item >> 9]);   // 512 items per chunk
    }

    // ---- qfc: s-major samples (availability matches publish order) ----
    for (int r = wq; r < NSAMP; r += NWARP_WORK) {
        int s = r >> 7;
        unsigned* flag = &g_lstm_s[s];
        while (ld_acq(flag) < (unsigned)B_SZ) __nanosleep(128);
        qfc_sample(r, l, ops, phiq, Whead, b_head, out);
    }
}

// ---------------------------------------------------------------------------
// Host: numpy-legacy MT19937 (RandomState(1234)) -> ops + wire permutation
// ---------------------------------------------------------------------------
namespace {

struct MT19937 {
    uint32_t mt[624];
    int mti;
    void seed(uint32_t s) {
        mt[0] = s;
        for (int i = 1; i < 624; i++)
            mt[i] = 1812433253u * (mt[i - 1] ^ (mt[i - 1] >> 30)) + (uint32_t)i;
        mti = 624;
    }
    uint32_t next() {
        if (mti >= 624) {
            for (int k = 0; k < 624; k++) {
                uint32_t y = (mt[k] & 0x80000000u) | (mt[(k + 1) % 624] & 0x7fffffffu);
                mt[k] = mt[(k + 397) % 624] ^ (y >> 1) ^ ((y & 1u) ? 0x9908b0dfu : 0u);
            }
            mti = 0;
        }
        uint32_t y = mt[mti++];
        y ^= y >> 11;
        y ^= (y << 7)  & 0x9d2c5680u;
        y ^= (y << 15) & 0xefc60000u;
        y ^= y >> 18;
        return y;
    }
    uint32_t randint(uint32_t n) {
        uint32_t mx = n - 1;
        if (mx == 0) return 0;
        uint32_t mask = mx;
        mask |= mask >> 1; mask |= mask >> 2; mask |= mask >> 4;
        mask |= mask >> 8; mask |= mask >> 16;
        uint32_t v;
        do { v = next() & mask; } while (v > mx);
        return v;
    }
    double rdouble() {
        uint32_t a = next() >> 5, b2 = next() >> 6;
        return (a * 67108864.0 + b2) / 9007199254740992.0;
    }
};

void build_ops(QOps& o) {
    int kind[N_OPS], wa[N_OPS], wb[N_OPS];
    float cc[N_OPS], ss[N_OPS];

    MT19937 mt;
    mt.seed(1234u);
    int freq[8] = {0};
    for (int n = 0; n < N_OPS; n++) {
        uint32_t k = mt.randint(4);
        if (k == 3) {
            int c = (int)mt.randint(8);
            int t = (int)mt.randint(7);
            if (t >= c) t++;
            kind[n] = 3; wa[n] = c; wb[n] = t;
            cc[n] = 0.f; ss[n] = 0.f;
            freq[c]++; freq[t]++;
        } else {
            int w = (int)mt.randint(8);
            double ang = mt.rdouble() * (2.0 * M_PI);
            float angf = (float)ang;
            kind[n] = (int)(k % 3); wa[n] = w; wb[n] = 0;
            cc[n] = cosf(angf * 0.5f);
            ss[n] = sinf(angf * 0.5f);
            freq[w]++;
        }
    }

    // Wire -> bit position: 3 hottest wires get k-bit positions (5,6,7).
    int order[8] = {0, 1, 2, 3, 4, 5, 6, 7};
    for (int i = 0; i < 8; i++)           // stable selection sort by freq desc
        for (int j = i + 1; j < 8; j++)
            if (freq[order[j]] > freq[order[i]]) {
                int t = order[i]; order[i] = order[j]; order[j] = t;
            }
    int pos[8];
    for (int j = 0; j < 3; j++) { o.ord[5 + j] = order[j]; pos[order[j]] = 5 + j; }
    for (int j = 0; j < 5; j++) { o.ord[j] = order[3 + j]; pos[order[3 + j]] = j; }

    for (int n = 0; n < N_OPS; n++) {
        o.kind[n] = kind[n];
        o.pa[n]   = pos[wa[n]];
        o.pb[n]   = (kind[n] == 3) ? pos[wb[n]] : 0;
        o.c[n]    = cc[n];
        o.s[n]    = ss[n];
    }
}

} // namespace

// ---------------------------------------------------------------------------
extern "C" void kernel_launch(void* const* d_in, const int* in_sizes, int n_in,
                              void* d_out, int out_size)
{
    const float* emb    = (const float*)d_in[0];
    const float* Win    = (const float*)d_in[1];
    const float* b_in   = (const float*)d_in[2];
    const float* phi    = (const float*)d_in[3];
    const float* Wout   = (const float*)d_in[4];
    const float* b_out  = (const float*)d_in[5];
    const float* phiq   = (const float*)d_in[6];
    const float* Whead  = (const float*)d_in[7];
    const float* b_head = (const float*)d_in[8];
    const void*  sent   = (const void*)d_in[9];

    QOps ops;
    build_ops(ops);   // deterministic, recomputed every call

    k_init <<<1, 128>>>();
    k_fused<<<NBLK, THREADS>>>(emb, Win, b_in, phi, Wout, b_out,
                               phiq, Whead, b_head, sent,
                               (float*)d_out, ops);
}

// round 17
// speedup vs baseline: 1.8256x; 1.8256x over previous
#include <cuda_runtime.h>
#include <math.h>
#include <stdint.h>

#ifndef M_PI
#define M_PI 3.14159265358979323846
#endif

#define S_LEN 128
#define B_SZ  128
#define T_OUT 12
#define NSAMP (S_LEN * B_SZ)   // 16384
#define N_OPS 30
#define MAXOPS 40

// ---------------------------------------------------------------------------
// Scratch (device globals; no allocation allowed)
// ---------------------------------------------------------------------------
__device__ float g_zx[NSAMP * 32];      // [s*B+b][g*8+q]
__device__ float g_h [NSAMP * 8];       // [s*B+b][h]
__device__ float4 g_F0[8], g_F1[8];     // final per-bit-position U = RX(phiq)*Tr

// Compiled circuit (host-generated each call, passed by value)
// kinds: 0=rx 1=ry 2=rz (c,s), 3=cnot, 4=general U (u0,u1)
// u0 = (U00.re,U00.im,U01.re,U01.im); u1 = (U10.re,U10.im,U11.re,U11.im)
struct QOps {
    int    n_mid;
    int    kind[MAXOPS];
    int    pa[MAXOPS];     // bit position (<5 lane, >=5 register/k)
    int    pb[MAXOPS];     // cnot target bit position
    float  c[MAXOPS], s[MAXOPS];
    float4 u0[MAXOPS], u1[MAXOPS];
    float4 A0[8], A1[8];   // leading U per bit position j (rows)
    float4 Tr0[8], Tr1[8]; // trailing U per bit position j (rows)
    int    ord[8];         // ord[j] = original wire at bit position j
};

// ---------------------------------------------------------------------------
__device__ __forceinline__ float fast_sigmoid(float x) {
    return __fdividef(1.f, 1.f + __expf(-x));
}
__device__ __forceinline__ float fast_tanh(float x) {
    x = fminf(fmaxf(x, -15.f), 15.f);
    float t = __expf(2.f * x);
    return __fdividef(t - 1.f, t + 1.f);
}

// ---------------------------------------------------------------------------
// Init kernel: compute final gates F_j = RX(phiq[ord[j]]) * Tr_j  (8 threads)
// ---------------------------------------------------------------------------
__global__ void k_init(const float* __restrict__ phiq, QOps ops) {
    int t = threadIdx.x;
    if (t < 8) {
        float sr, cr;
        sincosf(0.5f * phiq[ops.ord[t]], &sr, &cr);
        float4 t0 = ops.Tr0[t], t1 = ops.Tr1[t];
        // RX rows: [(cr,0), (0,-sr); (0,-sr), (cr,0)]
        g_F0[t] = make_float4(cr * t0.x + sr * t1.y,  cr * t0.y - sr * t1.x,
                              cr * t0.z + sr * t1.w,  cr * t0.w - sr * t1.z);
        g_F1[t] = make_float4(sr * t0.y + cr * t1.x, -sr * t0.x + cr * t1.y,
                              sr * t0.w + cr * t1.z, -sr * t0.z + cr * t1.w);
    }
}

// ---------------------------------------------------------------------------
// Kernel 1: embedding gather + input projection. 4 samples/warp, float4 rows.
// ---------------------------------------------------------------------------
__global__ void __launch_bounds__(256) k_embed(
        const float* __restrict__ emb,
        const float* __restrict__ Win,
        const float* __restrict__ b_in,
        const float* __restrict__ phi,
        const void*  __restrict__ sent_raw)
{
    __shared__ float winT[64 * 32];  // [e][l]
    __shared__ float bp[32];

    int tid = threadIdx.x;
    for (int k = tid; k < 64 * 32; k += 256) {
        int e = k >> 5, l = k & 31;
        winT[k] = Win[l * 72 + e];
    }
    if (tid < 32) bp[tid] = b_in[tid] + phi[tid];
    __syncthreads();

    // dtype sniff: int64 sentence has all-zero high words (tokens < 30000)
    const int* si = (const int*)sent_raw;
    bool is64 = true;
    #pragma unroll
    for (int k = 0; k < 16; k++)
        if (si[2 * k + 1] != 0) is64 = false;

    int wid = tid >> 5, l = tid & 31;
    int sb0 = blockIdx.x * 32 + wid * 4;

    long long t0 = is64 ? ((const long long*)sent_raw)[sb0 + 0] : (long long)si[sb0 + 0];
    long long t1 = is64 ? ((const long long*)sent_raw)[sb0 + 1] : (long long)si[sb0 + 1];
    long long t2 = is64 ? ((const long long*)sent_raw)[sb0 + 2] : (long long)si[sb0 + 2];
    long long t3 = is64 ? ((const long long*)sent_raw)[sb0 + 3] : (long long)si[sb0 + 3];
    const float4* e0 = (const float4*)(emb + t0 * 64);
    const float4* e1 = (const float4*)(emb + t1 * 64);
    const float4* e2 = (const float4*)(emb + t2 * 64);
    const float4* e3 = (const float4*)(emb + t3 * 64);

    float a0 = bp[l], a1 = a0, a2 = a0, a3 = a0;
    #pragma unroll
    for (int e4 = 0; e4 < 16; e4++) {
        float4 v0 = e0[e4], v1 = e1[e4], v2 = e2[e4], v3 = e3[e4];
        float w0 = winT[(e4 * 4 + 0) * 32 + l];
        float w1 = winT[(e4 * 4 + 1) * 32 + l];
        float w2 = winT[(e4 * 4 + 2) * 32 + l];
        float w3 = winT[(e4 * 4 + 3) * 32 + l];
        a0 = fmaf(v0.x, w0, fmaf(v0.y, w1, fmaf(v0.z, w2, fmaf(v0.w, w3, a0))));
        a1 = fmaf(v1.x, w0, fmaf(v1.y, w1, fmaf(v1.z, w2, fmaf(v1.w, w3, a1))));
        a2 = fmaf(v2.x, w0, fmaf(v2.y, w1, fmaf(v2.z, w2, fmaf(v2.w, w3, a2))));
        a3 = fmaf(v3.x, w0, fmaf(v3.y, w1, fmaf(v3.z, w2, fmaf(v3.w, w3, a3))));
    }
    g_zx[(sb0 + 0) * 32 + l] = a0;
    g_zx[(sb0 + 1) * 32 + l] = a1;
    g_zx[(sb0 + 2) * 32 + l] = a2;
    g_zx[(sb0 + 3) * 32 + l] = a3;
}

// ---------------------------------------------------------------------------
// Kernel 2: LSTM recurrence. One warp per batch element b, one warp/SM.
// ---------------------------------------------------------------------------
__global__ void __launch_bounds__(32) k_lstm(
        const float* __restrict__ Win,
        const float* __restrict__ Wout,
        const float* __restrict__ b_out)
{
    const unsigned FULL = 0xffffffffu;
    int b = blockIdx.x;
    int l = threadIdx.x;
    int g = l >> 3, h = l & 7;

    float winh[8], wo[8];
    #pragma unroll
    for (int j = 0; j < 8; j++) {
        winh[j] = Win[l * 72 + 64 + j];
        wo[j]   = Wout[(g * 8 + h) * 8 + j];
    }
    float bo = b_out[g * 8 + h];

    float cst = 0.f, hh = 0.f;
    float zbuf = g_zx[b * 32 + l];
    for (int s = 0; s < S_LEN; s++) {
        float z = zbuf;
        if (s + 1 < S_LEN)
            zbuf = g_zx[((s + 1) * B_SZ + b) * 32 + l];

        #pragma unroll
        for (int j = 0; j < 8; j++)
            z = fmaf(__shfl_sync(FULL, hh, j), winh[j], z);

        float cz = __cosf(z);
        float cj[8];
        #pragma unroll
        for (int j = 0; j < 8; j++)
            cj[j] = __shfl_sync(FULL, cz, (g << 3) | j);

        // pre = bo + c0*(W0 + c1*(W1 + ...)) == sum_q W_q * cumprod_q
        float t = wo[7];
        #pragma unroll
        for (int j = 6; j >= 0; j--)
            t = fmaf(cj[j + 1], t, wo[j]);
        float pre = fmaf(cj[0], t, bo);

        float pf = __shfl_sync(FULL, pre, h);
        float pi = __shfl_sync(FULL, pre, 8  | h);
        float pg = __shfl_sync(FULL, pre, 16 | h);
        float po = __shfl_sync(FULL, pre, 24 | h);

        float fg = fast_sigmoid(pf);
        float ig = fast_sigmoid(pi);
        float gg = fast_tanh(pg);
        float og = fast_sigmoid(po);

        cst = fmaf(fg, cst, ig * gg);
        hh  = og * fast_tanh(cst);

        if (l < 8) g_h[(s * B_SZ + b) * 8 + l] = hh;
        __syncwarp();
    }
}

// ---------------------------------------------------------------------------
// QFC: register statevector, compiled circuit.
// Lane l holds amps i = k*32 + l. Index bits 0..4 = lane bits, 5..7 = k bits.
// ---------------------------------------------------------------------------
#define RXP(i,j) do { float nx0=c*ax[i]+sn*ay[j], ny0=c*ay[i]-sn*ax[j]; \
                      float nx1=c*ax[j]+sn*ay[i], ny1=c*ay[j]-sn*ax[i]; \
                      ax[i]=nx0; ay[i]=ny0; ax[j]=nx1; ay[j]=ny1; } while(0)
#define RYP(i,j) do { float nx0=c*ax[i]-sn*ax[j], ny0=c*ay[i]-sn*ay[j]; \
                      float nx1=sn*ax[i]+c*ax[j], ny1=sn*ay[i]+c*ay[j]; \
                      ax[i]=nx0; ay[i]=ny0; ax[j]=nx1; ay[j]=ny1; } while(0)
#define SWP(i,j) do { float tx=ax[i]; ax[i]=ax[j]; ax[j]=tx; \
                      float ty=ay[i]; ay[i]=ay[j]; ay[j]=ty; } while(0)
#define UGEN(i,j) do { \
    float nix = u0.x*ax[i] - u0.y*ay[i] + u0.z*ax[j] - u0.w*ay[j]; \
    float niy = u0.x*ay[i] + u0.y*ax[i] + u0.z*ay[j] + u0.w*ax[j]; \
    float njx = u1.x*ax[i] - u1.y*ay[i] + u1.z*ax[j] - u1.w*ay[j]; \
    float njy = u1.x*ay[i] + u1.y*ax[i] + u1.z*ay[j] + u1.w*ax[j]; \
    ax[i]=nix; ay[i]=niy; ax[j]=njx; ay[j]=njy; } while(0)
#define PAIRS_SWITCH(kb, APPLY) \
    switch (kb) { \
      case 0:  APPLY(0,1); APPLY(2,3); APPLY(4,5); APPLY(6,7); break; \
      case 1:  APPLY(0,2); APPLY(1,3); APPLY(4,6); APPLY(5,7); break; \
      default: APPLY(0,4); APPLY(1,5); APPLY(2,6); APPLY(3,7); break; \
    }

// General U on bit position p (works for lane and k bits)
__device__ __forceinline__ void apply_u(float ax[8], float ay[8], int l, int p,
                                        float4 u0, float4 u1)
{
    const unsigned FULL = 0xffffffffu;
    if (p < 5) {
        unsigned m = 1u << p;
        bool bit = (l >> p) & 1;
        float car = bit ? u1.z : u0.x, cai = bit ? u1.w : u0.y;
        float cbr = bit ? u1.x : u0.z, cbi = bit ? u1.y : u0.w;
        #pragma unroll
        for (int k = 0; k < 8; k++) {
            float px = __shfl_xor_sync(FULL, ax[k], m);
            float py = __shfl_xor_sync(FULL, ay[k], m);
            float nx = car * ax[k] - cai * ay[k] + cbr * px - cbi * py;
            float ny = car * ay[k] + cai * ax[k] + cbr * py + cbi * px;
            ax[k] = nx; ay[k] = ny;
        }
    } else {
        PAIRS_SWITCH(p - 5, UGEN);
    }
}

__global__ void __launch_bounds__(256) k_qfc(
        const float* __restrict__ Whead,
        const float* __restrict__ b_head,
        float* __restrict__ out,
        QOps ops)
{
    const unsigned FULL = 0xffffffffu;
    int tid = threadIdx.x, l = tid & 31;
    int r = blockIdx.x * 8 + (tid >> 5);
    int s = r & 127, b = r >> 7;        // flat row r = b*S + s

    const float* th = &g_h[(s * B_SZ + b) * 8];

    // Per bit position j: complex pair (v0, v1) = A_j * (cos(h/2), sin(h/2))
    float v0r[8], v0i[8], v1r[8], v1i[8];
    #pragma unroll
    for (int j = 0; j < 8; j++) {
        float cc, ss;
        __sincosf(0.5f * th[ops.ord[j]], &ss, &cc);
        float4 a0 = ops.A0[j], a1 = ops.A1[j];
        v0r[j] = a0.x * cc + a0.z * ss;  v0i[j] = a0.y * cc + a0.w * ss;
        v1r[j] = a1.x * cc + a1.z * ss;  v1i[j] = a1.y * cc + a1.w * ss;
    }

    // Product-state init with complex per-wire amplitudes
    float br_ = (l & 1) ? v1r[0] : v0r[0];
    float bi_ = (l & 1) ? v1i[0] : v0i[0];
    #pragma unroll
    for (int j = 1; j < 5; j++) {
        float sr2 = ((l >> j) & 1) ? v1r[j] : v0r[j];
        float si2 = ((l >> j) & 1) ? v1i[j] : v0i[j];
        float nr = br_ * sr2 - bi_ * si2;
        float ni = br_ * si2 + bi_ * sr2;
        br_ = nr; bi_ = ni;
    }

    float ax[8], ay[8];
    #pragma unroll
    for (int k = 0; k < 8; k++) {
        float ar  = (k & 1)        ? v1r[5] : v0r[5];
        float ai  = (k & 1)        ? v1i[5] : v0i[5];
        float br2 = ((k >> 1) & 1) ? v1r[6] : v0r[6];
        float bi2 = ((k >> 1) & 1) ? v1i[6] : v0i[6];
        float cr2 = ((k >> 2) & 1) ? v1r[7] : v0r[7];
        float ci2 = ((k >> 2) & 1) ? v1i[7] : v0i[7];
        float tr = ar * br2 - ai * bi2, ti = ar * bi2 + ai * br2;
        float ur = tr * cr2 - ti * ci2, ui = tr * ci2 + ti * cr2;
        ax[k] = br_ * ur - bi_ * ui;
        ay[k] = br_ * ui + bi_ * ur;
    }

    // Compiled mid-circuit gates — uniform control flow
    for (int op = 0; op < ops.n_mid; op++) {
        int kind = ops.kind[op];
        int pa   = ops.pa[op];

        if (kind == 3) {                              // ---- CNOT ----
            int pc = pa, pt = ops.pb[op];
            if (pc < 5 && pt < 5) {
                unsigned m = 1u << pt;
                bool ctl = (l >> pc) & 1;
                #pragma unroll
                for (int k = 0; k < 8; k++) {
                    float qx = __shfl_xor_sync(FULL, ax[k], m);
                    float qy = __shfl_xor_sync(FULL, ay[k], m);
                    if (ctl) { ax[k] = qx; ay[k] = qy; }
                }
            } else if (pc < 5) {
                bool ctl = (l >> pc) & 1;
                if (ctl) { PAIRS_SWITCH(pt - 5, SWP); }
            } else if (pt < 5) {
                unsigned m = 1u << pt;
                int ckb = pc - 5;
                #pragma unroll
                for (int k = 0; k < 8; k++) {
                    float qx = __shfl_xor_sync(FULL, ax[k], m);
                    float qy = __shfl_xor_sync(FULL, ay[k], m);
                    if ((k >> ckb) & 1) { ax[k] = qx; ay[k] = qy; }
                }
            } else {
                int ckb = pc - 5, tkb = pt - 5;
                switch (ckb * 4 + tkb) {
                  case 1:  SWP(1,3); SWP(5,7); break;
                  case 2:  SWP(1,5); SWP(3,7); break;
                  case 4:  SWP(2,3); SWP(6,7); break;
                  case 6:  SWP(2,6); SWP(3,7); break;
                  case 8:  SWP(4,5); SWP(6,7); break;
                  default: SWP(4,6); SWP(5,7); break;
                }
            }
        } else if (kind == 4) {                       // ---- general U ----
            apply_u(ax, ay, l, pa, ops.u0[op], ops.u1[op]);
        } else if (kind == 2) {                       // ---- RZ ----
            float c = ops.c[op], sn = ops.s[op];
            if (pa < 5) {
                float sg = ((l >> pa) & 1) ? -sn : sn;
                #pragma unroll
                for (int k = 0; k < 8; k++) {
                    float x = ax[k], y = ay[k];
                    ax[k] = c * x + sg * y;
                    ay[k] = c * y - sg * x;
                }
            } else {
                int kb = pa - 5;
                #pragma unroll
                for (int k = 0; k < 8; k++) {
                    float sg = ((k >> kb) & 1) ? -sn : sn;
                    float x = ax[k], y = ay[k];
                    ax[k] = c * x + sg * y;
                    ay[k] = c * y - sg * x;
                }
            }
        } else if (kind == 1) {                       // ---- RY ----
            float c = ops.c[op], sn = ops.s[op];
            if (pa < 5) {
                unsigned m = 1u << pa;
                float sg = ((l >> pa) & 1) ? sn : -sn;
                #pragma unroll
                for (int k = 0; k < 8; k++) {
                    float px = __shfl_xor_sync(FULL, ax[k], m);
                    float py = __shfl_xor_sync(FULL, ay[k], m);
                    ax[k] = c * ax[k] + sg * px;
                    ay[k] = c * ay[k] + sg * py;
                }
            } else {
                PAIRS_SWITCH(pa - 5, RYP);
            }
        } else {                                      // ---- RX ----
            float c = ops.c[op], sn = ops.s[op];
            if (pa < 5) {
                unsigned m = 1u << pa;
                #pragma unroll
                for (int k = 0; k < 8; k++) {
                    float px = __shfl_xor_sync(FULL, ax[k], m);
                    float py = __shfl_xor_sync(FULL, ay[k], m);
                    ax[k] = c * ax[k] + sn * py;
                    ay[k] = c * ay[k] - sn * px;
                }
            } else {
                PAIRS_SWITCH(pa - 5, RXP);
            }
        }
    }

    // Final per-wire gates F_j = RX(phiq)*Tr_j (p = j is compile-time here)
    #pragma unroll
    for (int j = 0; j < 8; j++)
        apply_u(ax, ay, l, j, g_F0[j], g_F1[j]);

    // Measure <Z> per bit position
    float pb4[8];
    #pragma unroll
    for (int k = 0; k < 8; k++) pb4[k] = ax[k] * ax[k] + ay[k] * ay[k];

    float P = ((pb4[0] + pb4[1]) + (pb4[2] + pb4[3])) +
              ((pb4[4] + pb4[5]) + (pb4[6] + pb4[7]));
    float mb0 = (pb4[0] + pb4[2] + pb4[4] + pb4[6]) - (pb4[1] + pb4[3] + pb4[5] + pb4[7]);
    float mb1 = (pb4[0] + pb4[1] + pb4[4] + pb4[5]) - (pb4[2] + pb4[3] + pb4[6] + pb4[7]);
    float mb2 = (pb4[0] + pb4[1] + pb4[2] + pb4[3]) - (pb4[4] + pb4[5] + pb4[6] + pb4[7]);

    float z[8];
    #pragma unroll
    for (int j = 0; j < 5; j++)
        z[j] = ((l >> j) & 1) ? -P : P;
    z[5] = mb0; z[6] = mb1; z[7] = mb2;

    #pragma unroll
    for (int off = 16; off >= 1; off >>= 1) {
        #pragma unroll
        for (int j = 0; j < 8; j++)
            z[j] += __shfl_xor_sync(FULL, z[j], off);
    }

    // Head + log_softmax (lanes 0..11); permutation folded into Whead index
    float lg = -INFINITY;
    if (l < T_OUT) {
        lg = b_head[l];
        #pragma unroll
        for (int j = 0; j < 8; j++)
            lg = fmaf(Whead[l * 8 + ops.ord[j]], z[j], lg);
    }
    float m = lg;
    #pragma unroll
    for (int off = 16; off >= 1; off >>= 1)
        m = fmaxf(m, __shfl_xor_sync(FULL, m, off));
    float e = (l < T_OUT) ? expf(lg - m) : 0.f;
    float se = e;
    #pragma unroll
    for (int off = 16; off >= 1; off >>= 1)
        se += __shfl_xor_sync(FULL, se, off);

    if (l < T_OUT)
        out[(b * S_LEN + s) * T_OUT + l] = lg - m - logf(se);
}

// ---------------------------------------------------------------------------
// Host: MT19937 op generation + circuit compiler
// ---------------------------------------------------------------------------
namespace {

struct MT19937 {
    uint32_t mt[624];
    int mti;
    void seed(uint32_t s) {
        mt[0] = s;
        for (int i = 1; i < 624; i++)
            mt[i] = 1812433253u * (mt[i - 1] ^ (mt[i - 1] >> 30)) + (uint32_t)i;
        mti = 624;
    }
    uint32_t next() {
        if (mti >= 624) {
            for (int k = 0; k < 624; k++) {
                uint32_t y = (mt[k] & 0x80000000u) | (mt[(k + 1) % 624] & 0x7fffffffu);
                mt[k] = mt[(k + 397) % 624] ^ (y >> 1) ^ ((y & 1u) ? 0x9908b0dfu : 0u);
            }
            mti = 0;
        }
        uint32_t y = mt[mti++];
        y ^= y >> 11;
        y ^= (y << 7)  & 0x9d2c5680u;
        y ^= (y << 15) & 0xefc60000u;
        y ^= y >> 18;
        return y;
    }
    uint32_t randint(uint32_t n) {   // numpy legacy masked rejection
        uint32_t mx = n - 1;
        if (mx == 0) return 0;
        uint32_t mask = mx;
        mask |= mask >> 1; mask |= mask >> 2; mask |= mask >> 4;
        mask |= mask >> 8; mask |= mask >> 16;
        uint32_t v;
        do { v = next() & mask; } while (v > mx);
        return v;
    }
    double rdouble() {
        uint32_t a = next() >> 5, b2 = next() >> 6;
        return (a * 67108864.0 + b2) / 9007199254740992.0;
    }
};

struct C2 { double re, im; };
static inline C2 cmulh(C2 a, C2 b) {
    return { a.re * b.re - a.im * b.im, a.re * b.im + a.im * b.re };
}
struct M2 { C2 m[2][2]; };
static inline M2 ident2() {
    M2 r; r.m[0][0] = {1, 0}; r.m[0][1] = {0, 0};
    r.m[1][0] = {0, 0}; r.m[1][1] = {1, 0};
    return r;
}
static inline M2 mmul(const M2& A, const M2& B) {   // A * B
    M2 r;
    for (int i = 0; i < 2; i++)
        for (int j = 0; j < 2; j++) {
            C2 p = cmulh(A.m[i][0], B.m[0][j]);
            C2 q = cmulh(A.m[i][1], B.m[1][j]);
            r.m[i][j] = { p.re + q.re, p.im + q.im };
        }
    return r;
}
static inline M2 rotm(int kind, float c, float s) {
    M2 r;
    if (kind == 0) {        // RX
        r.m[0][0] = {c, 0}; r.m[0][1] = {0, -s};
        r.m[1][0] = {0, -s}; r.m[1][1] = {c, 0};
    } else if (kind == 1) { // RY
        r.m[0][0] = {c, 0}; r.m[0][1] = {-s, 0};
        r.m[1][0] = {s, 0}; r.m[1][1] = {c, 0};
    } else {                // RZ: diag(e^{-it}, e^{+it}), t = theta/2
        r.m[0][0] = {c, -s}; r.m[0][1] = {0, 0};
        r.m[1][0] = {0, 0};  r.m[1][1] = {c, s};
    }
    return r;
}
static inline void pack_rows(const M2& U, float4& r0, float4& r1) {
    r0 = make_float4((float)U.m[0][0].re, (float)U.m[0][0].im,
                     (float)U.m[0][1].re, (float)U.m[0][1].im);
    r1 = make_float4((float)U.m[1][0].re, (float)U.m[1][0].im,
                     (float)U.m[1][1].re, (float)U.m[1][1].im);
}

struct MidOp { int kind, wa, wb; float c, s; M2 U; };

void build_ops(QOps& o) {
    // ---- 1. raw random layer (numpy RandomState(1234)) ----
    int rk[N_OPS], rwa[N_OPS], rwb[N_OPS];
    float rc[N_OPS], rs[N_OPS];
    MT19937 mt;
    mt.seed(1234u);
    for (int n = 0; n < N_OPS; n++) {
        uint32_t k = mt.randint(4);
        if (k == 3) {
            int c = (int)mt.randint(8);
            int t = (int)mt.randint(7);
            if (t >= c) t++;
            rk[n] = 3; rwa[n] = c; rwb[n] = t; rc[n] = 0.f; rs[n] = 0.f;
        } else {
            int w = (int)mt.randint(8);
            double ang = mt.rdouble() * (2.0 * M_PI);
            float angf = (float)ang;             // reference casts to f32
            rk[n] = (int)(k % 3); rwa[n] = w; rwb[n] = 0;
            rc[n] = cosf(angf * 0.5f);
            rs[n] = sinf(angf * 0.5f);
        }
    }

    // ---- 2. compile: merge rotation runs per wire ----
    M2 pend[8], A[8], Tr[8];
    int nrot[8] = {0};
    int lr_kind[8]; float lr_c[8], lr_s[8];      // last (single) rotation
    bool touched[8] = {false};
    for (int w = 0; w < 8; w++) { pend[w] = ident2(); A[w] = ident2(); }

    MidOp mids[MAXOPS];
    int nmid = 0;

    auto flush = [&](int u) {
        if (nrot[u] == 0) return;
        if (!touched[u]) {
            A[u] = pend[u];                       // leading -> init
        } else if (nrot[u] == 1) {
            mids[nmid++] = { lr_kind[u], u, 0, lr_c[u], lr_s[u], ident2() };
        } else {
            mids[nmid++] = { 4, u, 0, 0.f, 0.f, pend[u] };
        }
        pend[u] = ident2();
        nrot[u] = 0;
    };

    for (int n = 0; n < N_OPS; n++) {
        if (rk[n] == 3) {
            int c = rwa[n], t = rwb[n];
            flush(c); touched[c] = true;
            flush(t); touched[t] = true;
            mids[nmid++] = { 3, c, t, 0.f, 0.f, ident2() };
        } else {
            int w = rwa[n];
            pend[w] = mmul(rotm(rk[n], rc[n], rs[n]), pend[w]);
            nrot[w]++;
            lr_kind[w] = rk[n]; lr_c[w] = rc[n]; lr_s[w] = rs[n];
        }
    }
    for (int w = 0; w < 8; w++) Tr[w] = pend[w];  // trailing (device merges RX(phiq))

    // ---- 3. wire -> bit position by mid-op frequency ----
    int freq[8] = {0};
    for (int n = 0; n < nmid; n++) {
        freq[mids[n].wa]++;
        if (mids[n].kind == 3) freq[mids[n].wb]++;
    }
    int order[8] = {0, 1, 2, 3, 4, 5, 6, 7};
    for (int i = 0; i < 8; i++)
        for (int j = i + 1; j < 8; j++)
            if (freq[order[j]] > freq[order[i]]) {
                int t = order[i]; order[i] = order[j]; order[j] = t;
            }
    int pos[8];
    for (int j = 0; j < 3; j++) { o.ord[5 + j] = order[j];     pos[order[j]]     = 5 + j; }
    for (int j = 0; j < 5; j++) { o.ord[j]     = order[3 + j]; pos[order[3 + j]] = j;     }

    // ---- 4. fill QOps ----
    o.n_mid = nmid;
    for (int n = 0; n < nmid; n++) {
        o.kind[n] = mids[n].kind;
        o.pa[n]   = pos[mids[n].wa];
        o.pb[n]   = (mids[n].kind == 3) ? pos[mids[n].wb] : 0;
        o.c[n]    = mids[n].c;
        o.s[n]    = mids[n].s;
        pack_rows(mids[n].U, o.u0[n], o.u1[n]);
    }
    for (int n = nmid; n < MAXOPS; n++) {
        o.kind[n] = 0; o.pa[n] = 0; o.pb[n] = 0; o.c[n] = 1.f; o.s[n] = 0.f;
        pack_rows(ident2(), o.u0[n], o.u1[n]);
    }
    for (int j = 0; j < 8; j++) {
        pack_rows(A[o.ord[j]],  o.A0[j],  o.A1[j]);
        pack_rows(Tr[o.ord[j]], o.Tr0[j], o.Tr1[j]);
    }
}

} // namespace

// ---------------------------------------------------------------------------
extern "C" void kernel_launch(void* const* d_in, const int* in_sizes, int n_in,
                              void* d_out, int out_size)
{
    const float* emb    = (const float*)d_in[0];
    const float* Win    = (const float*)d_in[1];
    const float* b_in   = (const float*)d_in[2];
    const float* phi    = (const float*)d_in[3];
    const float* Wout   = (const float*)d_in[4];
    const float* b_out  = (const float*)d_in[5];
    const float* phiq   = (const float*)d_in[6];
    const float* Whead  = (const float*)d_in[7];
    const float* b_head = (const float*)d_in[8];
    const void*  sent   = (const void*)d_in[9];

    QOps ops;
    build_ops(ops);   // deterministic, recomputed every call

    k_init <<<1, 32>>>(phiq, ops);
    k_embed<<<NSAMP / 32, 256>>>(emb, Win, b_in, phi, sent);
    k_lstm <<<B_SZ, 32>>>(Win, Wout, b_out);
    k_qfc  <<<NSAMP / 8, 256>>>(Whead, b_head, (float*)d_out, ops);
}